// round 13
// baseline (speedup 1.0000x reference)
#include <cuda_runtime.h>

#define BB 2
#define LL 2048
#define DD 1024
#define NS 16
#define RR 64
#define EE 96
#define NC 64
#define LC 32    /* LL / NC */
#define SST 16   /* subtile steps (2 per chunk) */
#define ML (BB*LL)

typedef unsigned long long u64;
typedef unsigned int u32;

// ---------------- packed f32x2 helpers ----------------
__device__ __forceinline__ u64 pk2(float x, float y) {
    u64 r; asm("mov.b64 %0,{%1,%2};" : "=l"(r) : "f"(x), "f"(y)); return r;
}
__device__ __forceinline__ float2 upk(u64 v) {
    float2 f; asm("mov.b64 {%0,%1},%2;" : "=f"(f.x), "=f"(f.y) : "l"(v)); return f;
}
__device__ __forceinline__ u64 fma2_(u64 a, u64 b, u64 c) {
    u64 d; asm("fma.rn.f32x2 %0,%1,%2,%3;" : "=l"(d) : "l"(a), "l"(b), "l"(c)); return d;
}
__device__ __forceinline__ u64 mul2_(u64 a, u64 b) {
    u64 d; asm("mul.rn.f32x2 %0,%1,%2;" : "=l"(d) : "l"(a), "l"(b)); return d;
}
#define CP_ASYNC16(dst_u32, src_ptr) \
    asm volatile("cp.async.cg.shared.global [%0], [%1], 16;" :: "r"(dst_u32), "l"(src_ptr))
#define CP_COMMIT() asm volatile("cp.async.commit_group;")
#define CP_WAIT(n)  asm volatile("cp.async.wait_group %0;" :: "n"(n))

// ---------------- scratch ----------------
__device__ float g_part[8 * ML * EE];
__device__ float g_xdbl[ML*EE];             // (m,96): [0:64)=dt_in, [64:80)=B, [80:96)=C
__device__ float g_dt[ML*DD];
__device__ float g_a0[DD];
__device__ int   g_chain[DD];
__device__ u64   g_P  [NC*BB*DD*8];
__device__ u64   g_S  [NC*BB*DD*8];
__device__ u64   g_hin[NC*BB*DD*8];

// =========================================================================
// init: per-d a0 + chain flag
// =========================================================================
__global__ void init_a0(const float* __restrict__ A_log)
{
    int d = blockIdx.x * 256 + threadIdx.x;
    if (d >= DD) return;
    float a0 = -__expf(A_log[d*NS]);
    bool chain = true;
    #pragma unroll
    for (int n = 1; n < NS; n++) {
        float an = -__expf(A_log[d*NS + n]);
        chain = chain && (fabsf(an - (float)(n+1)*a0) <= 2e-5f*(float)(n+1));
    }
    g_a0[d] = a0;
    g_chain[d] = chain ? 1 : 0;
}

// =========================================================================
// GEMM1 (split-K partials) — r5 config
// =========================================================================
#define G1_BM 64
#define G1_BN 96
#define G1_BK 32
#define G1_KC 128

__global__ void __launch_bounds__(96) gemm1_partial(
    const float* __restrict__ X, const float* __restrict__ Wx)
{
    __shared__ float As[G1_BK][G1_BM + 4];
    __shared__ float Bs[G1_BK][G1_BN + 4];
    const int t  = threadIdx.x;
    const int tx = t % 12;
    const int ty = t / 12;
    const int m0 = blockIdx.x * G1_BM;
    const int ks = blockIdx.y;

    u64 acc[8][4];
    #pragma unroll
    for (int i = 0; i < 8; i++)
        #pragma unroll
        for (int j = 0; j < 4; j++) acc[i][j] = 0ull;

    for (int kt = 0; kt < G1_KC / G1_BK; kt++) {
        const int k0 = ks * G1_KC + kt * G1_BK;
        for (int i = t; i < 512; i += 96) {
            int row = i >> 3, q = i & 7;
            float4 v = *(const float4*)&X[(m0 + row) * DD + k0 + q * 4];
            As[q*4+0][row] = v.x; As[q*4+1][row] = v.y;
            As[q*4+2][row] = v.z; As[q*4+3][row] = v.w;
        }
        for (int i = t; i < 768; i += 96) {
            int n = i >> 3, q = i & 7;
            float4 v = *(const float4*)&Wx[n * DD + k0 + q * 4];
            Bs[q*4+0][n] = v.x; Bs[q*4+1][n] = v.y;
            Bs[q*4+2][n] = v.z; Bs[q*4+3][n] = v.w;
        }
        __syncthreads();
        #pragma unroll
        for (int kk = 0; kk < G1_BK; kk++) {
            float4 av0 = *(const float4*)&As[kk][ty * 8];
            float4 av1 = *(const float4*)&As[kk][ty * 8 + 4];
            ulonglong2 bq0 = *(const ulonglong2*)&Bs[kk][tx * 8];
            ulonglong2 bq1 = *(const ulonglong2*)&Bs[kk][tx * 8 + 4];
            u64 b2[4] = {bq0.x, bq0.y, bq1.x, bq1.y};
            float a[8] = {av0.x, av0.y, av0.z, av0.w, av1.x, av1.y, av1.z, av1.w};
            #pragma unroll
            for (int i = 0; i < 8; i++) {
                u64 a2 = pk2(a[i], a[i]);
                #pragma unroll
                for (int j = 0; j < 4; j++)
                    acc[i][j] = fma2_(a2, b2[j], acc[i][j]);
            }
        }
        __syncthreads();
    }

    float* outp = g_part + (size_t)ks * (ML*EE);
    #pragma unroll
    for (int i = 0; i < 8; i++) {
        int m = m0 + ty * 8 + i;
        float2 p0 = upk(acc[i][0]), p1 = upk(acc[i][1]);
        float2 p2 = upk(acc[i][2]), p3 = upk(acc[i][3]);
        *(float4*)&outp[m * EE + tx * 8]     = make_float4(p0.x, p0.y, p1.x, p1.y);
        *(float4*)&outp[m * EE + tx * 8 + 4] = make_float4(p2.x, p2.y, p3.x, p3.y);
    }
}

__global__ void __launch_bounds__(256) gemm1_reduce()
{
    const int i = blockIdx.x * 256 + threadIdx.x;      // < 98304
    const float4* p = (const float4*)g_part;
    float4 s = p[i];
    #pragma unroll
    for (int ks = 1; ks < 8; ks++) {
        float4 v = p[(size_t)ks * 98304 + i];
        s.x += v.x; s.y += v.y; s.z += v.z; s.w += v.w;
    }
    ((float4*)g_xdbl)[i] = s;
}

// =========================================================================
// GEMM2 + softplus — r5 config
// =========================================================================
__global__ void __launch_bounds__(128) gemm2_softplus(
    const float* __restrict__ Wdt, const float* __restrict__ bdt)
{
    __shared__ float As[32][64 + 4];
    __shared__ float Bs[32][128 + 4];
    const int t  = threadIdx.x;
    const int tx = t % 16;
    const int ty = t / 16;
    const int m0 = blockIdx.x * 64;
    const int n0 = blockIdx.y * 128;

    u64 acc[8][4];
    #pragma unroll
    for (int i = 0; i < 8; i++)
        #pragma unroll
        for (int j = 0; j < 4; j++) acc[i][j] = 0ull;

    for (int kt = 0; kt < 2; kt++) {
        const int k0 = kt * 32;
        for (int i = t; i < 512; i += 128) {
            int row = i >> 3, q = i & 7;
            float4 v = *(const float4*)&g_xdbl[(m0 + row) * EE + k0 + q * 4];
            As[q*4+0][row] = v.x; As[q*4+1][row] = v.y;
            As[q*4+2][row] = v.z; As[q*4+3][row] = v.w;
        }
        for (int i = t; i < 1024; i += 128) {
            int n = i >> 3, q = i & 7;
            float4 v = *(const float4*)&Wdt[(n0 + n) * RR + k0 + q * 4];
            Bs[q*4+0][n] = v.x; Bs[q*4+1][n] = v.y;
            Bs[q*4+2][n] = v.z; Bs[q*4+3][n] = v.w;
        }
        __syncthreads();
        #pragma unroll
        for (int kk = 0; kk < 32; kk++) {
            float4 av0 = *(const float4*)&As[kk][ty * 8];
            float4 av1 = *(const float4*)&As[kk][ty * 8 + 4];
            ulonglong2 bq0 = *(const ulonglong2*)&Bs[kk][tx * 8];
            ulonglong2 bq1 = *(const ulonglong2*)&Bs[kk][tx * 8 + 4];
            u64 b2[4] = {bq0.x, bq0.y, bq1.x, bq1.y};
            float a[8] = {av0.x, av0.y, av0.z, av0.w, av1.x, av1.y, av1.z, av1.w};
            #pragma unroll
            for (int i = 0; i < 8; i++) {
                u64 a2 = pk2(a[i], a[i]);
                #pragma unroll
                for (int j = 0; j < 4; j++)
                    acc[i][j] = fma2_(a2, b2[j], acc[i][j]);
            }
        }
        __syncthreads();
    }

    float4 bi0 = *(const float4*)&bdt[n0 + tx * 8];
    float4 bi1 = *(const float4*)&bdt[n0 + tx * 8 + 4];
    float bi[8] = {bi0.x, bi0.y, bi0.z, bi0.w, bi1.x, bi1.y, bi1.z, bi1.w};
    #pragma unroll
    for (int i = 0; i < 8; i++) {
        int m = m0 + ty * 8 + i;
        float2 p[4] = {upk(acc[i][0]), upk(acc[i][1]), upk(acc[i][2]), upk(acc[i][3])};
        float v[8] = {p[0].x, p[0].y, p[1].x, p[1].y, p[2].x, p[2].y, p[3].x, p[3].y};
        #pragma unroll
        for (int j = 0; j < 8; j++) {
            float w = v[j] + bi[j];
            v[j] = (w > 20.f) ? w : log1pf(__expf(w));
        }
        *(float4*)&g_dt[m * DD + n0 + tx * 8]     = make_float4(v[0], v[1], v[2], v[3]);
        *(float4*)&g_dt[m * DD + n0 + tx * 8 + 4] = make_float4(v[4], v[5], v[6], v[7]);
    }
}

// ---------------- 4-entry packed ladder for this thread's half ----------------
__device__ __forceinline__ void pow_ladder4(float e1, int sub, u64* dA2) {
    float e2 = e1*e1, e4 = e2*e2, e8 = e4*e4;
    float sc = sub ? e8 : 1.f;
    float t1 = e1*sc, t2 = e2*sc;
    u64 d01 = pk2(t1, t2);
    u64 s2 = pk2(e2, e2), s4 = pk2(e4, e4);
    dA2[0] = d01;
    dA2[1] = mul2_(d01, s2);
    dA2[2] = mul2_(d01, s4);
    dA2[3] = mul2_(dA2[1], s4);
}

// =========================================================================
// pass 1: 128 thr, 64 channels pair-split, cp.async pipelined subtiles
// =========================================================================
__global__ void __launch_bounds__(128, 8) scan_pass1(
    const float* __restrict__ x, const float* __restrict__ A_log)
{
    __shared__ alignas(16) float Bsh[LC*NS];          // 2KB
    __shared__ alignas(16) float dts[2][SST][64];     // 8KB
    __shared__ alignas(16) float xs [2][SST][64];     // 8KB
    const int tid = threadIdx.x;
    const int sub = tid & 1;
    const int dl  = tid >> 1;                         // 0..63
    const int d0 = blockIdx.x*64;
    const int d = d0 + dl;
    const int b = blockIdx.y;
    const int c = blockIdx.z;
    const int l0 = c*LC;

    const float* dtg = g_dt + (size_t)(b*LL + l0)*DD + d0;
    const float* xg  = x    + (size_t)(b*LL + l0)*DD + d0;
    const u32 dts_a = (u32)__cvta_generic_to_shared(&dts[0][0][0]);
    const u32 xs_a  = (u32)__cvta_generic_to_shared(&xs[0][0][0]);

    // issue both subtiles' copies (group per subtile): 256 float4 per array per subtile
    #pragma unroll
    for (int s = 0; s < 2; s++) {
        #pragma unroll
        for (int i = 0; i < 2; i++) {
            int lin = tid + i*128;                    // 0..255
            int r = lin >> 4, q = lin & 15;
            u32 off = ((s*SST + r)*64 + q*4) * 4;
            CP_ASYNC16(dts_a + off, &dtg[(s*SST + r)*DD + q*4]);
            CP_ASYNC16(xs_a  + off, &xg [(s*SST + r)*DD + q*4]);
        }
        CP_COMMIT();
    }

    for (int i = tid; i < LC*NS; i += 128) {
        int l = i >> 4, n = i & 15;
        Bsh[i] = g_xdbl[(b*LL + l0 + l)*EE + RR + n];
    }

    const float a0 = g_a0[d];
    const bool chain = g_chain[d] != 0;
    const int baseK = ((c*BB + b)*DD + d)*8 + sub*4;

    u64 h2[4];
    #pragma unroll
    for (int k=0;k<4;k++) h2[k] = 0ull;
    float hg[8], Pg[8];
    #pragma unroll
    for (int n=0;n<8;n++) { hg[n]=0.f; Pg[n]=1.f; }
    float E = 1.f;
    float an[8];
    if (!chain) {
        #pragma unroll
        for (int n=0;n<8;n++) an[n] = -__expf(A_log[d*NS + sub*8 + n]);
    }

    #pragma unroll
    for (int s = 0; s < 2; s++) {
        if (s == 0) { CP_WAIT(1); } else { CP_WAIT(0); }
        __syncthreads();
        if (chain) {
            #pragma unroll 4
            for (int l = 0; l < SST; l++) {
                float dtv = dts[s][l][dl];
                float xv  = xs[s][l][dl];
                float dtx = dtv * xv;
                u64 dtx2 = pk2(dtx, dtx);
                float e1 = __expf(dtv * a0);
                E *= e1;
                u64 dA2[4];
                pow_ladder4(e1, sub, dA2);
                const u64* Bp = (const u64*)(Bsh + (s*SST + l)*NS) + sub*4;
                #pragma unroll
                for (int k=0;k<4;k++)
                    h2[k] = fma2_(dA2[k], h2[k], mul2_(dtx2, Bp[k]));
            }
        } else {
            for (int l = 0; l < SST; l++) {
                float dtv = dts[s][l][dl];
                float dtx = dtv * xs[s][l][dl];
                #pragma unroll
                for (int n=0;n<8;n++) {
                    float dA = __expf(dtv * an[n]);
                    Pg[n] *= dA;
                    hg[n] = fmaf(dA, hg[n], dtx*Bsh[(s*SST+l)*NS + sub*8 + n]);
                }
            }
        }
    }

    if (chain) {
        u64 P2[4];
        pow_ladder4(E, sub, P2);
        #pragma unroll
        for (int k=0;k<4;k++) { g_P[baseK+k] = P2[k]; g_S[baseK+k] = h2[k]; }
    } else {
        #pragma unroll
        for (int k=0;k<4;k++) { g_P[baseK+k] = pk2(Pg[2*k],Pg[2*k+1]); g_S[baseK+k] = pk2(hg[2*k],hg[2*k+1]); }
    }
}

// ---------------- pass 2: sequential chunk combine ----------------
__global__ void __launch_bounds__(256) scan_pass2()
{
    const int i = blockIdx.x*256 + threadIdx.x;     // over BB*DD*NS = 32768
    const float* Pf = (const float*)g_P;
    const float* Sf = (const float*)g_S;
    float* Hf = (float*)g_hin;
    float h = 0.f;
    #pragma unroll 8
    for (int c = 0; c < NC; c++) {
        int idx = c*(BB*DD*NS) + i;
        Hf[idx] = h;
        h = fmaf(Pf[idx], h, Sf[idx]);
    }
}

// =========================================================================
// pass 3: same structure + C dot + y output
// =========================================================================
__global__ void __launch_bounds__(128, 8) scan_pass3(
    const float* __restrict__ x, const float* __restrict__ A_log,
    const float* __restrict__ Dparam, float* __restrict__ out)
{
    __shared__ alignas(16) float Bsh[LC*NS];          // 2KB
    __shared__ alignas(16) float Csh[LC*NS];          // 2KB
    __shared__ alignas(16) float dts[2][SST][64];     // 8KB
    __shared__ alignas(16) float xs [2][SST][64];     // 8KB
    const int tid = threadIdx.x;
    const int sub = tid & 1;
    const int dl  = tid >> 1;
    const int d0 = blockIdx.x*64;
    const int d = d0 + dl;
    const int b = blockIdx.y;
    const int c = blockIdx.z;
    const int l0 = c*LC;

    const float* dtg = g_dt + (size_t)(b*LL + l0)*DD + d0;
    const float* xg  = x    + (size_t)(b*LL + l0)*DD + d0;
    const u32 dts_a = (u32)__cvta_generic_to_shared(&dts[0][0][0]);
    const u32 xs_a  = (u32)__cvta_generic_to_shared(&xs[0][0][0]);

    #pragma unroll
    for (int s = 0; s < 2; s++) {
        #pragma unroll
        for (int i = 0; i < 2; i++) {
            int lin = tid + i*128;
            int r = lin >> 4, q = lin & 15;
            u32 off = ((s*SST + r)*64 + q*4) * 4;
            CP_ASYNC16(dts_a + off, &dtg[(s*SST + r)*DD + q*4]);
            CP_ASYNC16(xs_a  + off, &xg [(s*SST + r)*DD + q*4]);
        }
        CP_COMMIT();
    }

    for (int i = tid; i < LC*NS; i += 128) {
        int l = i >> 4, n = i & 15;
        int base = (b*LL + l0 + l)*EE + RR;
        Bsh[i] = g_xdbl[base + n];
        Csh[i] = g_xdbl[base + NS + n];
    }

    const float a0 = g_a0[d];
    const bool chain = g_chain[d] != 0;
    const float Dp = Dparam[d];
    const int baseK = ((c*BB + b)*DD + d)*8 + sub*4;
    float* yp = out + (size_t)(b*LL + l0)*DD + d;

    u64 h2[4];
    #pragma unroll
    for (int k=0;k<4;k++) h2[k] = g_hin[baseK+k];
    float hg[8];
    #pragma unroll
    for (int k=0;k<4;k++) { float2 v = upk(h2[k]); hg[2*k]=v.x; hg[2*k+1]=v.y; }
    float an[8];
    if (!chain) {
        #pragma unroll
        for (int n=0;n<8;n++) an[n] = -__expf(A_log[d*NS + sub*8 + n]);
    }

    #pragma unroll
    for (int s = 0; s < 2; s++) {
        if (s == 0) { CP_WAIT(1); } else { CP_WAIT(0); }
        __syncthreads();
        if (chain) {
            #pragma unroll 4
            for (int l = 0; l < SST; l++) {
                float dtv = dts[s][l][dl];
                float xv  = xs[s][l][dl];
                float dtx = dtv * xv;
                u64 dtx2 = pk2(dtx, dtx);
                float e1 = __expf(dtv * a0);
                u64 dA2[4];
                pow_ladder4(e1, sub, dA2);
                const u64* Bp = (const u64*)(Bsh + (s*SST + l)*NS) + sub*4;
                const u64* Cp = (const u64*)(Csh + (s*SST + l)*NS) + sub*4;
                u64 y2 = 0ull;
                #pragma unroll
                for (int k=0;k<4;k++) {
                    h2[k] = fma2_(dA2[k], h2[k], mul2_(dtx2, Bp[k]));
                    y2 = fma2_(h2[k], Cp[k], y2);
                }
                float2 yy = upk(y2);
                float y_own = yy.x + yy.y;
                float y_tot = y_own + __shfl_xor_sync(0xFFFFFFFFu, y_own, 1);
                if (!sub) yp[(s*SST + l)*DD] = fmaf(xv, Dp, y_tot);
            }
        } else {
            for (int l = 0; l < SST; l++) {
                float dtv = dts[s][l][dl];
                float xv  = xs[s][l][dl];
                float dtx = dtv * xv;
                float y_own = 0.f;
                #pragma unroll
                for (int n=0;n<8;n++) {
                    float dA = __expf(dtv * an[n]);
                    hg[n] = fmaf(dA, hg[n], dtx*Bsh[(s*SST+l)*NS + sub*8 + n]);
                    y_own = fmaf(hg[n], Csh[(s*SST+l)*NS + sub*8 + n], y_own);
                }
                float y_tot = y_own + __shfl_xor_sync(0xFFFFFFFFu, y_own, 1);
                if (!sub) yp[(s*SST + l)*DD] = fmaf(xv, Dp, y_tot);
            }
        }
    }
}

// ---------------- launch ----------------
extern "C" void kernel_launch(void* const* d_in, const int* in_sizes, int n_in,
                              void* d_out, int out_size) {
    const float* x     = (const float*)d_in[0];
    const float* Wx    = (const float*)d_in[1];
    const float* Wdt   = (const float*)d_in[2];
    const float* bdt   = (const float*)d_in[3];
    const float* A_log = (const float*)d_in[4];
    const float* Dp    = (const float*)d_in[5];
    float* out = (float*)d_out;

    init_a0<<<(DD+255)/256, 256>>>(A_log);
    gemm1_partial<<<dim3(ML/G1_BM, 8), 96>>>(x, Wx);
    gemm1_reduce<<<ML*EE/4/256, 256>>>();
    gemm2_softplus<<<dim3(ML/64, DD/128), 128>>>(Wdt, bdt);

    scan_pass1<<<dim3(DD/64, BB, NC), 128>>>(x, A_log);
    scan_pass2<<<BB*DD*NS/256, 256>>>();
    scan_pass3<<<dim3(DD/64, BB, NC), 128>>>(x, A_log, Dp, out);
}

// round 14
// speedup vs baseline: 1.1146x; 1.1146x over previous
#include <cuda_runtime.h>

#define BB 2
#define LL 2048
#define DD 1024
#define NS 16
#define RR 64
#define EE 96
#define NC 32
#define LC 64   /* LL / NC */
#define ST 32   /* sub-tile steps staged in smem */
#define ML (BB*LL)

typedef unsigned long long u64;

// ---------------- packed f32x2 helpers ----------------
__device__ __forceinline__ u64 pk2(float x, float y) {
    u64 r; asm("mov.b64 %0,{%1,%2};" : "=l"(r) : "f"(x), "f"(y)); return r;
}
__device__ __forceinline__ float2 upk(u64 v) {
    float2 f; asm("mov.b64 {%0,%1},%2;" : "=f"(f.x), "=f"(f.y) : "l"(v)); return f;
}
__device__ __forceinline__ u64 fma2_(u64 a, u64 b, u64 c) {
    u64 d; asm("fma.rn.f32x2 %0,%1,%2,%3;" : "=l"(d) : "l"(a), "l"(b), "l"(c)); return d;
}
__device__ __forceinline__ u64 mul2_(u64 a, u64 b) {
    u64 d; asm("mul.rn.f32x2 %0,%1,%2;" : "=l"(d) : "l"(a), "l"(b)); return d;
}

// ---------------- scratch ----------------
__device__ float g_part[8 * ML * EE];        // GEMM1 split-K partials
__device__ float g_xdbl[ML*EE];              // (m,96): [0:64)=dt_in, [64:80)=B, [80:96)=C
__device__ float g_dt[ML*DD];                // softplus(dt_proj)
__device__ float g_a0[DD];
__device__ int   g_chain[DD];
// chunk state, layout [c][b][k][d] (k = packed-pair index 0..7) -> coalesced in d
__device__ u64   g_P  [NC*BB*8*DD];
__device__ u64   g_S  [NC*BB*8*DD];
__device__ u64   g_hin[NC*BB*8*DD];

// =========================================================================
// init: per-d a0 + chain flag
// =========================================================================
__global__ void init_a0(const float* __restrict__ A_log)
{
    int d = blockIdx.x * 256 + threadIdx.x;
    if (d >= DD) return;
    float a0 = -__expf(A_log[d*NS]);
    bool chain = true;
    #pragma unroll
    for (int n = 1; n < NS; n++) {
        float an = -__expf(A_log[d*NS + n]);
        chain = chain && (fabsf(an - (float)(n+1)*a0) <= 2e-5f*(float)(n+1));
    }
    g_a0[d] = a0;
    g_chain[d] = chain ? 1 : 0;
}

// =========================================================================
// GEMM1 (split-K partials) — r5 config, verbatim
// =========================================================================
#define G1_BM 64
#define G1_BN 96
#define G1_BK 32
#define G1_KC 128

__global__ void __launch_bounds__(96) gemm1_partial(
    const float* __restrict__ X, const float* __restrict__ Wx)
{
    __shared__ float As[G1_BK][G1_BM + 4];
    __shared__ float Bs[G1_BK][G1_BN + 4];
    const int t  = threadIdx.x;
    const int tx = t % 12;
    const int ty = t / 12;
    const int m0 = blockIdx.x * G1_BM;
    const int ks = blockIdx.y;

    u64 acc[8][4];
    #pragma unroll
    for (int i = 0; i < 8; i++)
        #pragma unroll
        for (int j = 0; j < 4; j++) acc[i][j] = 0ull;

    for (int kt = 0; kt < G1_KC / G1_BK; kt++) {
        const int k0 = ks * G1_KC + kt * G1_BK;
        for (int i = t; i < 512; i += 96) {
            int row = i >> 3, q = i & 7;
            float4 v = *(const float4*)&X[(m0 + row) * DD + k0 + q * 4];
            As[q*4+0][row] = v.x; As[q*4+1][row] = v.y;
            As[q*4+2][row] = v.z; As[q*4+3][row] = v.w;
        }
        for (int i = t; i < 768; i += 96) {
            int n = i >> 3, q = i & 7;
            float4 v = *(const float4*)&Wx[n * DD + k0 + q * 4];
            Bs[q*4+0][n] = v.x; Bs[q*4+1][n] = v.y;
            Bs[q*4+2][n] = v.z; Bs[q*4+3][n] = v.w;
        }
        __syncthreads();
        #pragma unroll
        for (int kk = 0; kk < G1_BK; kk++) {
            float4 av0 = *(const float4*)&As[kk][ty * 8];
            float4 av1 = *(const float4*)&As[kk][ty * 8 + 4];
            ulonglong2 bq0 = *(const ulonglong2*)&Bs[kk][tx * 8];
            ulonglong2 bq1 = *(const ulonglong2*)&Bs[kk][tx * 8 + 4];
            u64 b2[4] = {bq0.x, bq0.y, bq1.x, bq1.y};
            float a[8] = {av0.x, av0.y, av0.z, av0.w, av1.x, av1.y, av1.z, av1.w};
            #pragma unroll
            for (int i = 0; i < 8; i++) {
                u64 a2 = pk2(a[i], a[i]);
                #pragma unroll
                for (int j = 0; j < 4; j++)
                    acc[i][j] = fma2_(a2, b2[j], acc[i][j]);
            }
        }
        __syncthreads();
    }

    float* outp = g_part + (size_t)ks * (ML*EE);
    #pragma unroll
    for (int i = 0; i < 8; i++) {
        int m = m0 + ty * 8 + i;
        float2 p0 = upk(acc[i][0]), p1 = upk(acc[i][1]);
        float2 p2 = upk(acc[i][2]), p3 = upk(acc[i][3]);
        *(float4*)&outp[m * EE + tx * 8]     = make_float4(p0.x, p0.y, p1.x, p1.y);
        *(float4*)&outp[m * EE + tx * 8 + 4] = make_float4(p2.x, p2.y, p3.x, p3.y);
    }
}

__global__ void __launch_bounds__(256) gemm1_reduce()
{
    const int i = blockIdx.x * 256 + threadIdx.x;      // < 98304
    const float4* p = (const float4*)g_part;
    float4 s = p[i];
    #pragma unroll
    for (int ks = 1; ks < 8; ks++) {
        float4 v = p[(size_t)ks * 98304 + i];
        s.x += v.x; s.y += v.y; s.z += v.z; s.w += v.w;
    }
    ((float4*)g_xdbl)[i] = s;
}

// =========================================================================
// GEMM2 + softplus — r5 config, verbatim
// =========================================================================
__global__ void __launch_bounds__(128) gemm2_softplus(
    const float* __restrict__ Wdt, const float* __restrict__ bdt)
{
    __shared__ float As[32][64 + 4];
    __shared__ float Bs[32][128 + 4];
    const int t  = threadIdx.x;
    const int tx = t % 16;
    const int ty = t / 16;
    const int m0 = blockIdx.x * 64;
    const int n0 = blockIdx.y * 128;

    u64 acc[8][4];
    #pragma unroll
    for (int i = 0; i < 8; i++)
        #pragma unroll
        for (int j = 0; j < 4; j++) acc[i][j] = 0ull;

    for (int kt = 0; kt < 2; kt++) {
        const int k0 = kt * 32;
        for (int i = t; i < 512; i += 128) {
            int row = i >> 3, q = i & 7;
            float4 v = *(const float4*)&g_xdbl[(m0 + row) * EE + k0 + q * 4];
            As[q*4+0][row] = v.x; As[q*4+1][row] = v.y;
            As[q*4+2][row] = v.z; As[q*4+3][row] = v.w;
        }
        for (int i = t; i < 1024; i += 128) {
            int n = i >> 3, q = i & 7;
            float4 v = *(const float4*)&Wdt[(n0 + n) * RR + k0 + q * 4];
            Bs[q*4+0][n] = v.x; Bs[q*4+1][n] = v.y;
            Bs[q*4+2][n] = v.z; Bs[q*4+3][n] = v.w;
        }
        __syncthreads();
        #pragma unroll
        for (int kk = 0; kk < 32; kk++) {
            float4 av0 = *(const float4*)&As[kk][ty * 8];
            float4 av1 = *(const float4*)&As[kk][ty * 8 + 4];
            ulonglong2 bq0 = *(const ulonglong2*)&Bs[kk][tx * 8];
            ulonglong2 bq1 = *(const ulonglong2*)&Bs[kk][tx * 8 + 4];
            u64 b2[4] = {bq0.x, bq0.y, bq1.x, bq1.y};
            float a[8] = {av0.x, av0.y, av0.z, av0.w, av1.x, av1.y, av1.z, av1.w};
            #pragma unroll
            for (int i = 0; i < 8; i++) {
                u64 a2 = pk2(a[i], a[i]);
                #pragma unroll
                for (int j = 0; j < 4; j++)
                    acc[i][j] = fma2_(a2, b2[j], acc[i][j]);
            }
        }
        __syncthreads();
    }

    float4 bi0 = *(const float4*)&bdt[n0 + tx * 8];
    float4 bi1 = *(const float4*)&bdt[n0 + tx * 8 + 4];
    float bi[8] = {bi0.x, bi0.y, bi0.z, bi0.w, bi1.x, bi1.y, bi1.z, bi1.w};
    #pragma unroll
    for (int i = 0; i < 8; i++) {
        int m = m0 + ty * 8 + i;
        float2 p[4] = {upk(acc[i][0]), upk(acc[i][1]), upk(acc[i][2]), upk(acc[i][3])};
        float v[8] = {p[0].x, p[0].y, p[1].x, p[1].y, p[2].x, p[2].y, p[3].x, p[3].y};
        #pragma unroll
        for (int j = 0; j < 8; j++) {
            float w = v[j] + bi[j];
            v[j] = (w > 20.f) ? w : log1pf(__expf(w));
        }
        *(float4*)&g_dt[m * DD + n0 + tx * 8]     = make_float4(v[0], v[1], v[2], v[3]);
        *(float4*)&g_dt[m * DD + n0 + tx * 8 + 4] = make_float4(v[4], v[5], v[6], v[7]);
    }
}

// ---------------- packed power ladder: dA2[k] = (e1^(2k+1), e1^(2k+2)) ----------------
__device__ __forceinline__ void pow_ladder2(float e1, u64* dA2) {
    float e2 = e1*e1, e4 = e2*e2, e8 = e4*e4;
    u64 d01 = pk2(e1, e2);
    u64 s2 = pk2(e2, e2), s4 = pk2(e4, e4), s8 = pk2(e8, e8);
    dA2[0] = d01;
    dA2[1] = mul2_(d01, s2);
    dA2[2] = mul2_(d01, s4);
    dA2[3] = mul2_(dA2[1], s4);
    dA2[4] = mul2_(d01, s8);
    dA2[5] = mul2_(dA2[1], s8);
    dA2[6] = mul2_(dA2[2], s8);
    dA2[7] = mul2_(dA2[3], s8);
}

// ---------------- pass 1: r5 staging + coalesced P/S + init_a0 ----------------
__global__ void __launch_bounds__(128) scan_pass1(
    const float* __restrict__ x, const float* __restrict__ A_log)
{
    __shared__ alignas(16) float Bsh[LC*NS];        // 4KB
    __shared__ alignas(16) float dts[ST][128];      // 16KB
    __shared__ alignas(16) float xs [ST][128];      // 16KB
    const int tid = threadIdx.x;
    const int d0 = blockIdx.x*128;
    const int d = d0 + tid;
    const int b = blockIdx.y;
    const int c = blockIdx.z;
    const int l0 = c*LC;

    for (int i = tid; i < LC*NS; i += 128) {
        int l = i >> 4, n = i & 15;
        Bsh[i] = g_xdbl[(b*LL + l0 + l)*EE + RR + n];
    }

    const float a0 = g_a0[d];
    const bool chain = g_chain[d] != 0;

    const float* dtg = g_dt + (size_t)(b*LL + l0)*DD + d0;
    const float* xg  = x    + (size_t)(b*LL + l0)*DD + d0;
    const int cb8 = (c*BB + b)*8;          // state base: g_P[(cb8+k)*DD + d]

    u64 h2[8];
    #pragma unroll
    for (int k=0;k<8;k++) h2[k] = 0ull;
    float hg[NS], Pg[NS];
    #pragma unroll
    for (int n=0;n<NS;n++) { hg[n]=0.f; Pg[n]=1.f; }
    float E = 1.f;
    float an[NS];
    if (!chain) {
        #pragma unroll
        for (int n=0;n<NS;n++) an[n] = -__expf(A_log[d*NS+n]);
    }

    for (int s = 0; s < LC/ST; s++) {
        __syncthreads();
        #pragma unroll
        for (int i = 0; i < ST*32/128; i++) {
            int lin = tid + i*128;
            int r = lin >> 5, cc = lin & 31;
            *(float4*)&dts[r][cc*4] = *(const float4*)&dtg[(s*ST + r)*DD + cc*4];
            *(float4*)&xs [r][cc*4] = *(const float4*)&xg [(s*ST + r)*DD + cc*4];
        }
        __syncthreads();

        if (chain) {
            #pragma unroll 4
            for (int l = 0; l < ST; l++) {
                float dtv = dts[l][tid];
                float xv  = xs[l][tid];
                float dtx = dtv * xv;
                u64 dtx2 = pk2(dtx, dtx);
                float e1 = __expf(dtv * a0);
                E *= e1;
                u64 dA2[8];
                pow_ladder2(e1, dA2);
                const u64* Bp = (const u64*)(Bsh + (s*ST + l)*NS);
                #pragma unroll
                for (int k=0;k<8;k++)
                    h2[k] = fma2_(dA2[k], h2[k], mul2_(dtx2, Bp[k]));
            }
        } else {
            for (int l = 0; l < ST; l++) {
                float dtv = dts[l][tid];
                float dtx = dtv * xs[l][tid];
                #pragma unroll
                for (int n=0;n<NS;n++) {
                    float dA = __expf(dtv * an[n]);
                    Pg[n] *= dA;
                    hg[n] = fmaf(dA, hg[n], dtx*Bsh[(s*ST+l)*NS+n]);
                }
            }
        }
    }

    if (chain) {
        u64 P2[8];
        pow_ladder2(E, P2);
        #pragma unroll
        for (int k=0;k<8;k++) { g_P[(cb8+k)*DD + d] = P2[k]; g_S[(cb8+k)*DD + d] = h2[k]; }
    } else {
        #pragma unroll
        for (int k=0;k<8;k++) { g_P[(cb8+k)*DD + d] = pk2(Pg[2*k],Pg[2*k+1]); g_S[(cb8+k)*DD + d] = pk2(hg[2*k],hg[2*k+1]); }
    }
}

// ---------------- pass 2: sequential chunk combine (coalesced layout) ----------------
__global__ void __launch_bounds__(256) scan_pass2()
{
    const int i = blockIdx.x*256 + threadIdx.x;     // over BB*8*DD*2 floats = 32768
    const float* Pf = (const float*)g_P;
    const float* Sf = (const float*)g_S;
    float* Hf = (float*)g_hin;
    float h = 0.f;
    #pragma unroll
    for (int c = 0; c < NC; c++) {
        int idx = c*(BB*8*DD*2) + i;
        Hf[idx] = h;
        h = fmaf(Pf[idx], h, Sf[idx]);
    }
}

// ---------------- pass 3: r5 staging + coalesced hin + smem y staging ----------------
__global__ void __launch_bounds__(128) scan_pass3(
    const float* __restrict__ x, const float* __restrict__ A_log,
    const float* __restrict__ Dparam, float* __restrict__ out)
{
    __shared__ alignas(16) float Bsh[LC*NS];        // 4KB
    __shared__ alignas(16) float Csh[LC*NS];        // 4KB
    __shared__ alignas(16) float dts[ST][128];      // 16KB
    __shared__ alignas(16) float xs [ST][128];      // 16KB
    __shared__ alignas(16) float ysh[ST][128];      // 16KB
    const int tid = threadIdx.x;
    const int d0 = blockIdx.x*128;
    const int d = d0 + tid;
    const int b = blockIdx.y;
    const int c = blockIdx.z;
    const int l0 = c*LC;

    for (int i = tid; i < LC*NS; i += 128) {
        int l = i >> 4, n = i & 15;
        int base = (b*LL + l0 + l)*EE + RR;
        Bsh[i] = g_xdbl[base + n];
        Csh[i] = g_xdbl[base + NS + n];
    }

    const float a0 = g_a0[d];
    const bool chain = g_chain[d] != 0;
    const int cb8 = (c*BB + b)*8;
    const float Dp = Dparam[d];
    const float* dtg = g_dt + (size_t)(b*LL + l0)*DD + d0;
    const float* xg  = x    + (size_t)(b*LL + l0)*DD + d0;
    float* yg        = out  + (size_t)(b*LL + l0)*DD + d0;

    u64 h2[8];
    #pragma unroll
    for (int k=0;k<8;k++) h2[k] = g_hin[(cb8+k)*DD + d];
    float hg[NS];
    #pragma unroll
    for (int k=0;k<8;k++) { float2 v = upk(h2[k]); hg[2*k]=v.x; hg[2*k+1]=v.y; }
    float an[NS];
    if (!chain) {
        #pragma unroll
        for (int n=0;n<NS;n++) an[n] = -__expf(A_log[d*NS+n]);
    }

    for (int s = 0; s < LC/ST; s++) {
        __syncthreads();
        #pragma unroll
        for (int i = 0; i < ST*32/128; i++) {
            int lin = tid + i*128;
            int r = lin >> 5, cc = lin & 31;
            *(float4*)&dts[r][cc*4] = *(const float4*)&dtg[(s*ST + r)*DD + cc*4];
            *(float4*)&xs [r][cc*4] = *(const float4*)&xg [(s*ST + r)*DD + cc*4];
        }
        __syncthreads();

        if (chain) {
            #pragma unroll 4
            for (int l = 0; l < ST; l++) {
                float dtv = dts[l][tid];
                float xv  = xs[l][tid];
                float dtx = dtv * xv;
                u64 dtx2 = pk2(dtx, dtx);
                float e1 = __expf(dtv * a0);
                u64 dA2[8];
                pow_ladder2(e1, dA2);
                const u64* Bp = (const u64*)(Bsh + (s*ST + l)*NS);
                const u64* Cp = (const u64*)(Csh + (s*ST + l)*NS);
                u64 y2a = 0ull, y2b = 0ull;
                #pragma unroll
                for (int k=0;k<8;k+=2) {
                    h2[k]   = fma2_(dA2[k],   h2[k],   mul2_(dtx2, Bp[k]));
                    h2[k+1] = fma2_(dA2[k+1], h2[k+1], mul2_(dtx2, Bp[k+1]));
                    y2a = fma2_(h2[k],   Cp[k],   y2a);
                    y2b = fma2_(h2[k+1], Cp[k+1], y2b);
                }
                float2 ya = upk(y2a), yb = upk(y2b);
                ysh[l][tid] = fmaf(xv, Dp, (ya.x+ya.y)+(yb.x+yb.y));
            }
        } else {
            for (int l = 0; l < ST; l++) {
                float dtv = dts[l][tid];
                float xv  = xs[l][tid];
                float dtx = dtv * xv;
                float y = 0.f;
                #pragma unroll
                for (int n=0;n<NS;n++) {
                    float dA = __expf(dtv * an[n]);
                    hg[n] = fmaf(dA, hg[n], dtx*Bsh[(s*ST+l)*NS+n]);
                    y = fmaf(hg[n], Csh[(s*ST+l)*NS+n], y);
                }
                ysh[l][tid] = fmaf(xv, Dp, y);
            }
        }

        __syncthreads();
        // coalesced y write: 32 rows x 128 floats
        #pragma unroll
        for (int i = 0; i < ST*32/128; i++) {
            int lin = tid + i*128;
            int r = lin >> 5, cc = lin & 31;
            *(float4*)&yg[(s*ST + r)*DD + cc*4] = *(const float4*)&ysh[r][cc*4];
        }
    }
}

// ---------------- launch ----------------
extern "C" void kernel_launch(void* const* d_in, const int* in_sizes, int n_in,
                              void* d_out, int out_size) {
    const float* x     = (const float*)d_in[0];
    const float* Wx    = (const float*)d_in[1];
    const float* Wdt   = (const float*)d_in[2];
    const float* bdt   = (const float*)d_in[3];
    const float* A_log = (const float*)d_in[4];
    const float* Dp    = (const float*)d_in[5];
    float* out = (float*)d_out;

    init_a0<<<(DD+255)/256, 256>>>(A_log);
    gemm1_partial<<<dim3(ML/G1_BM, 8), 96>>>(x, Wx);
    gemm1_reduce<<<ML*EE/4/256, 256>>>();
    gemm2_softplus<<<dim3(ML/64, DD/128), 128>>>(Wdt, bdt);

    scan_pass1<<<dim3(DD/128, BB, NC), 128>>>(x, A_log);
    scan_pass2<<<BB*DD*NS/256, 256>>>();
    scan_pass3<<<dim3(DD/128, BB, NC), 128>>>(x, A_log, Dp, out);
}